// round 10
// baseline (speedup 1.0000x reference)
#include <cuda_runtime.h>
#include <math.h>

#define MAXB   4
#define MAXN   16384
#define MAXG   32
#define MAXPB  256       // focal partial slots per image
#define MAXAB  128       // assign partial slots per image (+1 fixup)
#define ABLK   256
#define FBLKS  64

#ifndef M_PI
#define M_PI 3.14159265358979323846
#endif

// ---------------- device scratch (no allocations allowed) ----------------
__device__ int                  g_lab[MAXB * MAXN];
__device__ float                g_mg[MAXB * MAXN * 5];
__device__ unsigned long long   g_best[MAXB * MAXG];
__device__ double               g_part[MAXB * MAXPB];            // focal-neg
__device__ double                g_part2[MAXB * (MAXAB + 1) * 3]; // corr partials
__device__ int                  g_cnt1[MAXB];
__device__ int                  g_cnt2;

// ---------------- helpers ----------------
__device__ __forceinline__ float jrem180(float x) {
    float r = fmodf(x, 180.0f);
    if (r < 0.0f) r += 180.0f;
    return r;
}

__device__ __forceinline__ float fl_neg(float x) {
    float e     = __expf(-x);
    float denom = 1.0f + e;
    float L     = __logf(denom);
    float inv   = __fdividef(1.0f, denom);
    return 0.75f * inv * inv * (L + x);
}

__device__ __forceinline__ float fl_pos(float x) {
    float e     = __expf(-x);
    float denom = 1.0f + e;
    float L     = __logf(denom);
    float inv   = __fdividef(1.0f, denom);
    float om    = e * inv;
    return 0.25f * om * om * L;
}

// smooth-L1 reg loss for anchor ab vs matched box mg, prediction br
__device__ __forceinline__ float reg_loss(const float* ab, const float* mg,
                                          const float* br)
{
    float dlt[5];
    dlt[0] = (mg[0] - ab[0]) / ab[2];
    dlt[1] = (mg[1] - ab[1]) / ab[3];
    dlt[2] = logf(mg[2] / ab[2]);
    dlt[3] = logf(mg[3] / ab[3]);
    dlt[4] = jrem180(mg[4] - ab[4] + 90.0f) - 90.0f;
    float l = 0.0f;
    #pragma unroll
    for (int k = 0; k < 4; k++) {
        float d = fabsf(br[k] - dlt[k]);
        l += (d < 1.0f) ? 0.5f * d * d : d - 0.5f;
    }
    float da = fabsf(jrem180(br[4] - dlt[4] + 90.0f) - 90.0f);
    l += (da < 1.0f) ? 0.5f * da * da : da - 0.5f;
    return l;
}

// Sutherland–Hodgman: clip convex CCW quad A by convex CCW quad B, shoelace area.
__device__ float quad_clip_area(const float* axp, const float* ayp,
                                const float* bxp, const float* byp)
{
    float Px[8], Py[8], Qx[8], Qy[8];
    int n = 4;
    #pragma unroll
    for (int k = 0; k < 4; k++) { Px[k] = axp[k]; Py[k] = ayp[k]; }

    #pragma unroll
    for (int j = 0; j < 4; j++) {
        float cx0 = bxp[j], cy0 = byp[j];
        int j1 = (j + 1) & 3;
        float ex = bxp[j1] - cx0, ey = byp[j1] - cy0;
        int m = 0;
        for (int k = 0; k < n; k++) {
            int k1 = (k + 1 == n) ? 0 : k + 1;
            float x0 = Px[k],  y0 = Py[k];
            float x1 = Px[k1], y1 = Py[k1];
            float d0 = ex * (y0 - cy0) - ey * (x0 - cx0);
            float d1 = ex * (y1 - cy0) - ey * (x1 - cx0);
            bool in0 = d0 >= 0.0f, in1 = d1 >= 0.0f;
            if (in0) { Qx[m] = x0; Qy[m] = y0; m++; }
            if (in0 != in1) {
                float t = d0 / (d0 - d1);
                Qx[m] = x0 + t * (x1 - x0);
                Qy[m] = y0 + t * (y1 - y0);
                m++;
            }
        }
        n = m;
        if (n == 0) break;
        for (int k = 0; k < n; k++) { Px[k] = Qx[k]; Py[k] = Qy[k]; }
    }

    if (n < 3) return 0.0f;
    float s = 0.0f;
    for (int k = 0; k < n; k++) {
        int k1 = (k + 1 == n) ? 0 : k + 1;
        s += Px[k] * Py[k1] - Px[k1] * Py[k];
    }
    return 0.5f * fabsf(s);
}

__device__ __forceinline__ void make_corners_f(float cx, float cy, float w,
                                               float h, float th,
                                               float* X, float* Y)
{
    float r = th * (float)(M_PI / 180.0);
    float s, c;
    __sincosf(r, &s, &c);
    float lx[4] = {-0.5f * w,  0.5f * w, 0.5f * w, -0.5f * w};
    float ly[4] = {-0.5f * h, -0.5f * h, 0.5f * h,  0.5f * h};
    #pragma unroll
    for (int k = 0; k < 4; k++) {
        X[k] = cx + lx[k] * c - ly[k] * s;
        Y[k] = cy + lx[k] * s + ly[k] * c;
    }
}

// final reduction (runs in the overall-last block)
__device__ void finalize(float* out, int B, int fblocks, int ablocks)
{
    int t = threadIdx.x;
    __shared__ double df[ABLK], dr[ABLK], dn[ABLK];
    double cls_m = 0.0, reg_m = 0.0;
    for (int bb = 0; bb < B; bb++) {
        double f = 0.0, r = 0.0, n = 0.0;
        for (int k = t; k < fblocks; k += ABLK)
            f += g_part[bb * MAXPB + k];
        for (int k = t; k < ablocks + 1; k += ABLK) {
            size_t o = (size_t)(bb * (MAXAB + 1) + k) * 3;
            f += g_part2[o + 0];
            r += g_part2[o + 1];
            n += g_part2[o + 2];
        }
        df[t] = f; dr[t] = r; dn[t] = n;
        __syncthreads();
        for (int s = ABLK / 2; s > 0; s >>= 1) {
            if (t < s) { df[t] += df[t+s]; dr[t] += dr[t+s]; dn[t] += dn[t+s]; }
            __syncthreads();
        }
        if (t == 0) {
            double npos = (dn[0] < 1.0) ? 1.0 : dn[0];
            cls_m += df[0] / npos;
            reg_m += dr[0] / npos;
        }
        __syncthreads();
    }
    if (t == 0) {
        cls_m /= (double)B;
        reg_m /= (double)B;
        out[0] = (float)(cls_m + reg_m);
        out[1] = (float)cls_m;
        out[2] = (float)reg_m;
        g_cnt2 = 0;
    }
}

// ---------------- the single kernel ----------------
__global__ __launch_bounds__(ABLK)
void mega_kernel(const float* __restrict__ anchors,
                 const float* __restrict__ gt_boxes,
                 const int*   __restrict__ gt_labels,
                 const float* __restrict__ logits,
                 const float* __restrict__ box_reg,
                 float* __restrict__ out,
                 int N, int G, int C, int B, int ablocks, int fblocks)
{
    int b = blockIdx.y;
    int t = threadIdx.x;
    int total_blocks = (int)(gridDim.x * gridDim.y);

    __shared__ int s_final;
    if (t == 0) s_final = 0;

    if ((int)blockIdx.x >= ablocks) {
        // ================= focal role =================
        int fb     = blockIdx.x - ablocks;
        int gtid   = fb * ABLK + t;
        int stride = fblocks * ABLK;
        int E  = N * C;
        int E4 = E >> 2;
        const float4* lp4 = (const float4*)(logits + (size_t)b * E);

        float acc = 0.0f;
        for (int q = gtid; q < E4; q += stride) {
            float4 v = lp4[q];
            acc += fl_neg(v.x) + fl_neg(v.y) + fl_neg(v.z) + fl_neg(v.w);
        }
        for (int e = (E4 << 2) + gtid; e < E; e += stride)
            acc += fl_neg(logits[(size_t)b * E + e]);

        __shared__ float sa[ABLK];
        sa[t] = acc;
        __syncthreads();
        for (int s = ABLK / 2; s > 0; s >>= 1) {
            if (t < s) sa[t] += sa[t + s];
            __syncthreads();
        }
        if (t == 0) {
            g_part[b * MAXPB + fb] = (double)sa[0];
            __threadfence();
            int v = atomicAdd(&g_cnt2, 1);
            if (v == total_blocks - 1) s_final = 1;
        }
        __syncthreads();
        if (s_final) finalize(out, B, fblocks, ablocks);
        return;
    }

    // ================= assign role =================
    int i0 = blockIdx.x * ABLK;
    int i  = i0 + t;

    __shared__ float sgx[MAXG][4], sgy[MAXG][4];
    __shared__ float sgb[MAXG][5];
    __shared__ float sg_sz[MAXG];
    __shared__ float sg_area[MAXG];
    __shared__ int   s_gl[MAXG];
    __shared__ unsigned long long s_best[MAXG];
    __shared__ unsigned long long s_bestA[ABLK];
    __shared__ float s_anc[ABLK][5];
    __shared__ float s_acx[ABLK][4], s_acy[ABLK][4];
    __shared__ unsigned short s_q[ABLK * MAXG / 2];
    __shared__ int   s_qn;
    __shared__ int   s_last;
    __shared__ float sf[ABLK], sr[ABLK], sn[ABLK];

    if (t == 0) { s_qn = 0; s_last = 0; }
    if (t < G) {
        const float* gb = gt_boxes + (size_t)(b * G + t) * 5;
        float w = gb[2], h = gb[3];
        #pragma unroll
        for (int k = 0; k < 5; k++) sgb[t][k] = gb[k];
        sg_sz[t]   = fmaxf(w, h);
        sg_area[t] = w * h;
        s_gl[t]    = gt_labels[b * G + t];
        make_corners_f(gb[0], gb[1], w, h, gb[4], sgx[t], sgy[t]);
        s_best[t] = 0ULL;
    }
    s_bestA[t] = 0ULL;
    if (i < N) {
        const float* ab = anchors + (size_t)i * 5;
        #pragma unroll
        for (int k = 0; k < 5; k++) s_anc[t][k] = ab[k];
        make_corners_f(ab[0], ab[1], ab[2], ab[3], ab[4], s_acx[t], s_acy[t]);
    }
    __syncthreads();

    // phase 1: gate -> pair queue
    if (i < N) {
        float ax = s_anc[t][0], ay = s_anc[t][1];
        float a_sz = fmaxf(s_anc[t][2], s_anc[t][3]);
        for (int j = 0; j < G; j++) {
            float dx = ax - sgb[j][0];
            float dy = ay - sgb[j][1];
            float gate = (a_sz + sg_sz[j]) * 0.7f;
            if (sqrtf(dx * dx + dy * dy) < gate) {
                int p = atomicAdd(&s_qn, 1);
                s_q[p] = (unsigned short)((t << 5) | j);
            }
        }
    }
    __syncthreads();

    // phase 2: drain queue; fold IoU into per-anchor / per-GT maxima
    int qn = s_qn;
    for (int q = t; q < qn; q += ABLK) {
        int e  = s_q[q];
        int li = e >> 5;
        int j  = e & 31;
        float a_area = s_anc[li][2] * s_anc[li][3];
        float inter = quad_clip_area(s_acx[li], s_acy[li], sgx[j], sgy[j]);
        float iou = inter / (a_area + sg_area[j] - inter + 1e-8f);
        if (iou > 0.0f) {
            unsigned long long ka =
                ((unsigned long long)__float_as_uint(iou) << 32)
                | (unsigned long long)(unsigned)(MAXG - 1 - j);
            atomicMax(&s_bestA[li], ka);
            unsigned long long kg =
                ((unsigned long long)__float_as_uint(iou) << 32)
                | (unsigned long long)(0xFFFFFFFFu - (unsigned)(i0 + li));
            atomicMax(&s_best[j], kg);
        }
    }
    __syncthreads();

    // phase 3: labels + per-anchor corrections (pre-force)
    float cf = 0.0f, rl = 0.0f, np = 0.0f;
    if (i < N) {
        unsigned long long ka = s_bestA[t];
        float best_iou = __uint_as_float((unsigned)(ka >> 32));
        int   best_j   = MAXG - 1 - (int)(ka & 31u);
        int lab;
        if (best_iou >= 0.5f) {
            lab = s_gl[best_j] + 1;
            #pragma unroll
            for (int k = 0; k < 5; k++)
                g_mg[(size_t)(b * MAXN + i) * 5 + k] = sgb[best_j][k];
        } else {
            lab = (best_iou < 0.4f) ? 0 : -1;
        }
        g_lab[b * MAXN + i] = lab;

        const float* lp = logits + ((size_t)b * N + i) * (size_t)C;
        if (lab < 0) {
            float s = 0.0f;
            for (int c = 0; c < C; c++) s += fl_neg(lp[c]);
            cf = -s;
        } else if (lab > 0) {
            float x = lp[lab - 1];
            cf = fl_pos(x) - fl_neg(x);
            np = 1.0f;
            rl = reg_loss(s_anc[t], sgb[best_j],
                          box_reg + ((size_t)b * N + i) * 5);
        }
    }

    sf[t] = cf; sr[t] = rl; sn[t] = np;
    __syncthreads();
    for (int s = ABLK / 2; s > 0; s >>= 1) {
        if (t < s) { sf[t] += sf[t + s]; sr[t] += sr[t + s]; sn[t] += sn[t + s]; }
        __syncthreads();
    }
    if (t == 0) {
        size_t o = (size_t)(b * (MAXAB + 1) + blockIdx.x) * 3;
        g_part2[o + 0] = (double)sf[0];
        g_part2[o + 1] = (double)sr[0];
        g_part2[o + 2] = (double)sn[0];
    }

    if (t < G && s_best[t] != 0ULL)
        atomicMax(&g_best[b * MAXG + t], s_best[t]);

    __syncthreads();
    if (t == 0) {
        __threadfence();
        int v = atomicAdd(&g_cnt1[b], 1);
        if (v == ablocks - 1) s_last = 1;
    }
    __syncthreads();

    // force-match tail: sequential G-loop + exact fix-up delta
    if (s_last && t == 0) {
        __threadfence();
        double dcf = 0.0, drl = 0.0, dnp = 0.0;
        for (int j = 0; j < G; j++) {
            unsigned long long key = g_best[b * MAXG + j];
            g_best[b * MAXG + j] = 0ULL;
            if ((key >> 32) != 0ULL) {
                int bi = (int)(0xFFFFFFFFu - (unsigned)(key & 0xFFFFFFFFu));
                int gl = s_gl[j] + 1;
                int old = g_lab[b * MAXN + bi];
                if (old != gl) {
                    const float* lp = logits + ((size_t)b * N + bi) * (size_t)C;
                    const float* ab = anchors + (size_t)bi * 5;
                    const float* br = box_reg + ((size_t)b * N + bi) * 5;
                    float* mgp = &g_mg[(size_t)(b * MAXN + bi) * 5];
                    // remove old contribution
                    if (old < 0) {
                        float s = 0.0f;
                        for (int c = 0; c < C; c++) s += fl_neg(lp[c]);
                        dcf += (double)s;            // minus (-s)
                    } else if (old > 0) {
                        float xo = lp[old - 1];
                        dcf -= (double)(fl_pos(xo) - fl_neg(xo));
                        drl -= (double)reg_loss(ab, mgp, br);
                        dnp -= 1.0;
                    }
                    // add new contribution
                    float xn = lp[gl - 1];
                    dcf += (double)(fl_pos(xn) - fl_neg(xn));
                    drl += (double)reg_loss(ab, sgb[j], br);
                    dnp += 1.0;
                    // commit
                    g_lab[b * MAXN + bi] = gl;
                    #pragma unroll
                    for (int k = 0; k < 5; k++) mgp[k] = sgb[j][k];
                }
            }
        }
        size_t o = (size_t)(b * (MAXAB + 1) + ablocks) * 3;
        g_part2[o + 0] = dcf;
        g_part2[o + 1] = drl;
        g_part2[o + 2] = dnp;
        g_cnt1[b] = 0;
    }
    __syncthreads();   // whole block waits for tail before counting done

    if (t == 0) {
        __threadfence();
        int v = atomicAdd(&g_cnt2, 1);
        if (v == total_blocks - 1) s_final = 1;
    }
    __syncthreads();
    if (s_final) finalize(out, B, fblocks, ablocks);
}

// ---------------- launch ----------------
extern "C" void kernel_launch(void* const* d_in, const int* in_sizes, int n_in,
                              void* d_out, int out_size)
{
    const float* logits  = (const float*)d_in[0];
    const float* breg    = (const float*)d_in[1];
    const float* anchors = (const float*)d_in[2];
    const float* gtb     = (const float*)d_in[3];
    const int*   gtl     = (const int*)d_in[4];

    int N = in_sizes[2] / 5;
    int B = in_sizes[1] / (5 * N);
    int C = in_sizes[0] / (B * N);
    int G = in_sizes[4] / B;

    int ablocks = (N + ABLK - 1) / ABLK;
    int fblocks = FBLKS;

    dim3 mg(ablocks + fblocks, B);
    mega_kernel<<<mg, ABLK>>>(anchors, gtb, gtl, logits, breg,
                              (float*)d_out, N, G, C, B, ablocks, fblocks);
}

// round 12
// speedup vs baseline: 1.7556x; 1.7556x over previous
#include <cuda_runtime.h>
#include <math.h>

#define MAXB   4
#define MAXN   16384
#define MAXG   32
#define MAXPB  256
#define ABLK   128       // anchors (and threads) per assign block
#define FBLKS  128       // focal blocks per image
#define KBLK   64        // finish kernel blocks per image
#define KTHR   256

#ifndef M_PI
#define M_PI 3.14159265358979323846
#endif

// ---------------- device scratch (no allocations allowed) ----------------
__device__ int                  g_lab[MAXB * MAXN];
__device__ float                g_mg[MAXB * MAXN * 5];
__device__ unsigned long long   g_best[MAXB * MAXG];
__device__ double               g_part[MAXB * MAXPB];        // focal-neg partials
__device__ double               g_part2[MAXB * KBLK * 3];    // correction partials
__device__ int                  g_cnt1[MAXB];
__device__ int                  g_cnt2;

// ---------------- helpers ----------------
__device__ __forceinline__ float jrem180(float x) {
    float r = fmodf(x, 180.0f);
    if (r < 0.0f) r += 180.0f;
    return r;
}

__device__ __forceinline__ float fl_neg(float x) {
    float e     = __expf(-x);
    float denom = 1.0f + e;
    float L     = __logf(denom);
    float inv   = __fdividef(1.0f, denom);
    return 0.75f * inv * inv * (L + x);
}

__device__ __forceinline__ float fl_pos(float x) {
    float e     = __expf(-x);
    float denom = 1.0f + e;
    float L     = __logf(denom);
    float inv   = __fdividef(1.0f, denom);
    float om    = e * inv;
    return 0.25f * om * om * L;
}

// Sutherland–Hodgman: clip convex CCW quad A by convex CCW quad B, shoelace area.
__device__ float quad_clip_area(const float* axp, const float* ayp,
                                const float* bxp, const float* byp)
{
    float Px[8], Py[8], Qx[8], Qy[8];
    int n = 4;
    #pragma unroll
    for (int k = 0; k < 4; k++) { Px[k] = axp[k]; Py[k] = ayp[k]; }

    #pragma unroll
    for (int j = 0; j < 4; j++) {
        float cx0 = bxp[j], cy0 = byp[j];
        int j1 = (j + 1) & 3;
        float ex = bxp[j1] - cx0, ey = byp[j1] - cy0;
        int m = 0;
        for (int k = 0; k < n; k++) {
            int k1 = (k + 1 == n) ? 0 : k + 1;
            float x0 = Px[k],  y0 = Py[k];
            float x1 = Px[k1], y1 = Py[k1];
            float d0 = ex * (y0 - cy0) - ey * (x0 - cx0);
            float d1 = ex * (y1 - cy0) - ey * (x1 - cx0);
            bool in0 = d0 >= 0.0f, in1 = d1 >= 0.0f;
            if (in0) { Qx[m] = x0; Qy[m] = y0; m++; }
            if (in0 != in1) {
                float t = d0 / (d0 - d1);
                Qx[m] = x0 + t * (x1 - x0);
                Qy[m] = y0 + t * (y1 - y0);
                m++;
            }
        }
        n = m;
        if (n == 0) break;
        for (int k = 0; k < n; k++) { Px[k] = Qx[k]; Py[k] = Qy[k]; }
    }

    if (n < 3) return 0.0f;
    float s = 0.0f;
    for (int k = 0; k < n; k++) {
        int k1 = (k + 1 == n) ? 0 : k + 1;
        s += Px[k] * Py[k1] - Px[k1] * Py[k];
    }
    return 0.5f * fabsf(s);
}

__device__ __forceinline__ void make_corners_f(float cx, float cy, float w,
                                               float h, float th,
                                               float* X, float* Y)
{
    float r = th * (float)(M_PI / 180.0);
    float s, c;
    __sincosf(r, &s, &c);
    float lx[4] = {-0.5f * w,  0.5f * w, 0.5f * w, -0.5f * w};
    float ly[4] = {-0.5f * h, -0.5f * h, 0.5f * h,  0.5f * h};
    #pragma unroll
    for (int k = 0; k < 4; k++) {
        X[k] = cx + lx[k] * c - ly[k] * s;
        Y[k] = cy + lx[k] * s + ly[k] * c;
    }
}

// ---------------- kernel 1: assign blocks ∥ focal-neg blocks --------------
__global__ __launch_bounds__(ABLK)
void mega_kernel(const float* __restrict__ anchors,
                 const float* __restrict__ gt_boxes,
                 const int*   __restrict__ gt_labels,
                 const float* __restrict__ logits,
                 int N, int G, int C, int ablocks, int fblocks)
{
    int b = blockIdx.y;
    int t = threadIdx.x;

    if ((int)blockIdx.x >= ablocks) {
        // ---- focal role: sum fl_neg over all logits (assignment-independent)
        int fb     = blockIdx.x - ablocks;
        int gtid   = fb * ABLK + t;
        int stride = fblocks * ABLK;
        int E  = N * C;
        int E4 = E >> 2;
        const float4* lp4 = (const float4*)(logits + (size_t)b * E);

        float acc = 0.0f;
        for (int q = gtid; q < E4; q += stride) {
            float4 v = lp4[q];
            acc += fl_neg(v.x) + fl_neg(v.y) + fl_neg(v.z) + fl_neg(v.w);
        }
        for (int e = (E4 << 2) + gtid; e < E; e += stride)
            acc += fl_neg(logits[(size_t)b * E + e]);

        __shared__ float sa[ABLK];
        sa[t] = acc;
        __syncthreads();
        for (int s = ABLK / 2; s > 0; s >>= 1) {
            if (t < s) sa[t] += sa[t + s];
            __syncthreads();
        }
        if (t == 0) g_part[b * MAXPB + fb] = (double)sa[0];
        return;
    }

    // ---- assign role ----
    int i0 = blockIdx.x * ABLK;
    int i  = i0 + t;

    __shared__ float sgx[MAXG][4], sgy[MAXG][4];
    __shared__ float sgb[MAXG][5];
    __shared__ float sg_sz[MAXG];
    __shared__ float sg_area[MAXG];
    __shared__ int   s_gl[MAXG];
    __shared__ unsigned long long s_best[MAXG];     // per-GT best anchor
    __shared__ unsigned long long s_bestA[ABLK];    // per-anchor best GT
    __shared__ float s_anc[ABLK][5];
    __shared__ float s_acx[ABLK][4], s_acy[ABLK][4];
    __shared__ unsigned short s_q[ABLK * 16];
    __shared__ int   s_qn;
    __shared__ int   s_last;

    if (t == 0) { s_qn = 0; s_last = 0; }
    if (t < G) {
        const float* gb = gt_boxes + (size_t)(b * G + t) * 5;
        float w = gb[2], h = gb[3];
        #pragma unroll
        for (int k = 0; k < 5; k++) sgb[t][k] = gb[k];
        sg_sz[t]   = fmaxf(w, h);
        sg_area[t] = w * h;
        s_gl[t]    = gt_labels[b * G + t];
        make_corners_f(gb[0], gb[1], w, h, gb[4], sgx[t], sgy[t]);
        s_best[t] = 0ULL;
    }
    s_bestA[t] = 0ULL;
    if (i < N) {
        const float* ab = anchors + (size_t)i * 5;
        #pragma unroll
        for (int k = 0; k < 5; k++) s_anc[t][k] = ab[k];
        make_corners_f(ab[0], ab[1], ab[2], ab[3], ab[4], s_acx[t], s_acy[t]);
    }
    __syncthreads();

    // phase 1: gate, build pair queue
    if (i < N) {
        float ax = s_anc[t][0], ay = s_anc[t][1];
        float a_sz = fmaxf(s_anc[t][2], s_anc[t][3]);
        for (int j = 0; j < G; j++) {
            float dx = ax - sgb[j][0];
            float dy = ay - sgb[j][1];
            float gate = (a_sz + sg_sz[j]) * 0.7f;
            if (sqrtf(dx * dx + dy * dy) < gate) {
                int p = atomicAdd(&s_qn, 1);
                s_q[p] = (unsigned short)((t << 5) | j);
            }
        }
    }
    __syncthreads();

    // phase 2: drain queue; fold IoU directly into per-anchor / per-GT maxima
    int qn = s_qn;
    for (int q = t; q < qn; q += ABLK) {
        int e  = s_q[q];
        int li = e >> 5;
        int j  = e & 31;
        float a_area = s_anc[li][2] * s_anc[li][3];
        float inter = quad_clip_area(s_acx[li], s_acy[li], sgx[j], sgy[j]);
        float iou = inter / (a_area + sg_area[j] - inter + 1e-8f);
        if (iou > 0.0f) {
            // per-anchor argmax, tie -> smaller j (first occurrence)
            unsigned long long ka =
                ((unsigned long long)__float_as_uint(iou) << 32)
                | (unsigned long long)(unsigned)(MAXG - 1 - j);
            atomicMax(&s_bestA[li], ka);
            // per-GT argmax over anchors, tie -> smaller anchor index
            unsigned long long kg =
                ((unsigned long long)__float_as_uint(iou) << 32)
                | (unsigned long long)(0xFFFFFFFFu - (unsigned)(i0 + li));
            atomicMax(&s_best[j], kg);
        }
    }
    __syncthreads();

    // phase 3: unpack per-anchor best, thresholds
    if (i < N) {
        unsigned long long ka = s_bestA[t];
        float best_iou = __uint_as_float((unsigned)(ka >> 32));
        int   best_j   = MAXG - 1 - (int)(ka & 31u);
        int lab;
        if (best_iou >= 0.5f) {
            lab = s_gl[best_j] + 1;
            #pragma unroll
            for (int k = 0; k < 5; k++)
                g_mg[(size_t)(b * MAXN + i) * 5 + k] = sgb[best_j][k];
        } else {
            lab = (best_iou < 0.4f) ? 0 : -1;
        }
        g_lab[b * MAXN + i] = lab;
    }
    __syncthreads();

    if (t < G && s_best[t] != 0ULL)
        atomicMax(&g_best[b * MAXG + t], s_best[t]);

    __syncthreads();
    if (t == 0) {
        __threadfence();
        int v = atomicAdd(&g_cnt1[b], 1);
        if (v == ablocks - 1) s_last = 1;
    }
    __syncthreads();
    if (s_last && t == 0) {
        __threadfence();
        for (int j = 0; j < G; j++) {
            unsigned long long key = g_best[b * MAXG + j];
            g_best[b * MAXG + j] = 0ULL;
            if ((key >> 32) != 0ULL) {
                int bi = (int)(0xFFFFFFFFu - (unsigned)(key & 0xFFFFFFFFu));
                int gl = s_gl[j] + 1;
                if (g_lab[b * MAXN + bi] != gl) {
                    g_lab[b * MAXN + bi] = gl;
                    #pragma unroll
                    for (int k = 0; k < 5; k++)
                        g_mg[(size_t)(b * MAXN + bi) * 5 + k] = sgb[j][k];
                }
            }
        }
        g_cnt1[b] = 0;
    }
}

// ---------------- kernel 2: corrections + reg + final reduce --------------
__global__ void finish_kernel(const float* __restrict__ logits,
                              const float* __restrict__ box_reg,
                              const float* __restrict__ anchors,
                              float* __restrict__ out,
                              int N, int C, int B, int fblocks)
{
    int b = blockIdx.y;
    int t = threadIdx.x;
    int gtid   = blockIdx.x * KTHR + t;
    int stride = gridDim.x * KTHR;

    float cf = 0.0f, rl = 0.0f, np = 0.0f;

    for (int i = gtid; i < N; i += stride) {
        int lab = g_lab[b * MAXN + i];
        if (lab < 0) {
            const float* lp = logits + ((size_t)b * N + i) * (size_t)C;
            float s = 0.0f;
            for (int c = 0; c < C; c++) s += fl_neg(lp[c]);
            cf -= s;
        } else if (lab > 0) {
            float x = logits[((size_t)b * N + i) * (size_t)C + (lab - 1)];
            cf += fl_pos(x) - fl_neg(x);
            np += 1.0f;
            const float* ab = anchors + (size_t)i * 5;
            const float* mg = &g_mg[(size_t)(b * MAXN + i) * 5];
            const float* br = box_reg + ((size_t)b * N + i) * 5;
            float dlt[5];
            dlt[0] = (mg[0] - ab[0]) / ab[2];
            dlt[1] = (mg[1] - ab[1]) / ab[3];
            dlt[2] = logf(mg[2] / ab[2]);
            dlt[3] = logf(mg[3] / ab[3]);
            dlt[4] = jrem180(mg[4] - ab[4] + 90.0f) - 90.0f;
            float l = 0.0f;
            #pragma unroll
            for (int k = 0; k < 4; k++) {
                float d = fabsf(br[k] - dlt[k]);
                l += (d < 1.0f) ? 0.5f * d * d : d - 0.5f;
            }
            float da = fabsf(jrem180(br[4] - dlt[4] + 90.0f) - 90.0f);
            l += (da < 1.0f) ? 0.5f * da * da : da - 0.5f;
            rl += l;
        }
    }

    __shared__ float sf[KTHR], sr[KTHR], sn[KTHR];
    __shared__ int   s_last;
    if (t == 0) s_last = 0;
    sf[t] = cf; sr[t] = rl; sn[t] = np;
    __syncthreads();
    for (int s = KTHR / 2; s > 0; s >>= 1) {
        if (t < s) { sf[t] += sf[t + s]; sr[t] += sr[t + s]; sn[t] += sn[t + s]; }
        __syncthreads();
    }
    if (t == 0) {
        size_t o = (size_t)(b * KBLK + blockIdx.x) * 3;
        g_part2[o + 0] = (double)sf[0];
        g_part2[o + 1] = (double)sr[0];
        g_part2[o + 2] = (double)sn[0];
        __threadfence();
        int total = (int)(gridDim.x * gridDim.y);
        int v = atomicAdd(&g_cnt2, 1);
        if (v == total - 1) s_last = 1;
    }
    __syncthreads();

    if (s_last) {
        if (t == 0) __threadfence();
        __syncthreads();
        __shared__ double df[KTHR], dr[KTHR], dn[KTHR];
        double cls_m = 0.0, reg_m = 0.0;
        for (int bb = 0; bb < B; bb++) {
            double f = 0.0, r = 0.0, n = 0.0;
            for (int k = t; k < fblocks; k += KTHR)
                f += g_part[bb * MAXPB + k];
            for (int k = t; k < KBLK; k += KTHR) {
                size_t o = (size_t)(bb * KBLK + k) * 3;
                f += g_part2[o + 0];
                r += g_part2[o + 1];
                n += g_part2[o + 2];
            }
            df[t] = f; dr[t] = r; dn[t] = n;
            __syncthreads();
            for (int s = KTHR / 2; s > 0; s >>= 1) {
                if (t < s) { df[t] += df[t+s]; dr[t] += dr[t+s]; dn[t] += dn[t+s]; }
                __syncthreads();
            }
            if (t == 0) {
                double npos = (dn[0] < 1.0) ? 1.0 : dn[0];
                cls_m += df[0] / npos;
                reg_m += dr[0] / npos;
            }
            __syncthreads();
        }
        if (t == 0) {
            cls_m /= (double)B;
            reg_m /= (double)B;
            out[0] = (float)(cls_m + reg_m);
            out[1] = (float)cls_m;
            out[2] = (float)reg_m;
            g_cnt2 = 0;
        }
    }
}

// ---------------- launch ----------------
extern "C" void kernel_launch(void* const* d_in, const int* in_sizes, int n_in,
                              void* d_out, int out_size)
{
    const float* logits  = (const float*)d_in[0];
    const float* breg    = (const float*)d_in[1];
    const float* anchors = (const float*)d_in[2];
    const float* gtb     = (const float*)d_in[3];
    const int*   gtl     = (const int*)d_in[4];

    int N = in_sizes[2] / 5;
    int B = in_sizes[1] / (5 * N);
    int C = in_sizes[0] / (B * N);
    int G = in_sizes[4] / B;

    int ablocks = (N + ABLK - 1) / ABLK;
    int fblocks = FBLKS;

    dim3 mg(ablocks + fblocks, B);
    mega_kernel<<<mg, ABLK>>>(anchors, gtb, gtl, logits, N, G, C,
                              ablocks, fblocks);

    dim3 fg(KBLK, B);
    finish_kernel<<<fg, KTHR>>>(logits, breg, anchors, (float*)d_out,
                                N, C, B, fblocks);
}

// round 13
// speedup vs baseline: 1.7799x; 1.0138x over previous
#include <cuda_runtime.h>
#include <math.h>

#define MAXB   4
#define MAXN   16384
#define MAXG   32
#define MAXPB  256
#define ABLK   128       // anchors (and threads) per assign block
#define FBLKS  128       // focal blocks per image
#define KBLK   64        // finish kernel blocks per image
#define KTHR   256

#ifndef M_PI
#define M_PI 3.14159265358979323846
#endif

// ---------------- device scratch (no allocations allowed) ----------------
__device__ int                  g_lab[MAXB * MAXN];
__device__ float                g_mg[MAXB * MAXN * 5];
__device__ unsigned long long   g_best[MAXB * MAXG];
__device__ double               g_part[MAXB * MAXPB];        // focal-neg partials
__device__ double               g_part2[MAXB * KBLK * 3];    // correction partials
__device__ int                  g_cnt1[MAXB];
__device__ int                  g_cnt2;

// ---------------- helpers ----------------
__device__ __forceinline__ float jrem180(float x) {
    float r = fmodf(x, 180.0f);
    if (r < 0.0f) r += 180.0f;
    return r;
}

__device__ __forceinline__ float fl_neg(float x) {
    float e     = __expf(-x);
    float denom = 1.0f + e;
    float L     = __logf(denom);
    float inv   = __fdividef(1.0f, denom);
    return 0.75f * inv * inv * (L + x);
}

__device__ __forceinline__ float fl_pos(float x) {
    float e     = __expf(-x);
    float denom = 1.0f + e;
    float L     = __logf(denom);
    float inv   = __fdividef(1.0f, denom);
    float om    = e * inv;
    return 0.25f * om * om * L;
}

// Sum over P's 4 edges of (t1-t0)*cross(a, r), where [t0,t1] is the parameter
// interval of the edge inside convex CCW quad Q. Fully register-resident:
// fractions compared via cross-multiplication, 1 division per edge.
// Intersection area = 0.5 * (arcs(P,Q) + arcs(Q,P)).
__device__ __forceinline__ float arcs_cross_sum(const float* Px, const float* Py,
                                                const float* Qx, const float* Qy)
{
    float acc = 0.0f;
    #pragma unroll
    for (int i = 0; i < 4; i++) {
        int i1 = (i + 1) & 3;
        float ax = Px[i], ay = Py[i];
        float rx = Px[i1] - ax, ry = Py[i1] - ay;
        float p = 0.0f, q = 1.0f;   // t0 = p/q  (q > 0)
        float r = 1.0f, s = 1.0f;   // t1 = r/s  (s > 0)
        bool empty = false;
        #pragma unroll
        for (int j = 0; j < 4; j++) {
            int j1 = (j + 1) & 3;
            float ex = Qx[j1] - Qx[j], ey = Qy[j1] - Qy[j];
            float d0 = ex * (ay - Qy[j]) - ey * (ax - Qx[j]);
            float d1 = d0 + ex * ry - ey * rx;
            if (d0 < 0.0f) {
                if (d1 < 0.0f) {
                    empty = true;           // edge fully outside this half-plane
                } else {
                    float n = -d0, den = d1 - d0;        // entering, den > 0
                    if (n * q > p * den) { p = n; q = den; }
                }
            } else if (d1 < 0.0f) {
                float n = d0, den = d0 - d1;             // exiting, den > 0
                if (n * s < r * den) { r = n; s = den; }
            }
        }
        float num = r * q - p * s;          // (t1 - t0) * (s*q), s*q > 0
        if (!empty && num > 0.0f)
            acc += num * __fdividef(ax * ry - rx * ay, s * q);
    }
    return acc;
}

__device__ __forceinline__ void make_corners_f(float cx, float cy, float w,
                                               float h, float th,
                                               float* X, float* Y)
{
    float r = th * (float)(M_PI / 180.0);
    float s, c;
    __sincosf(r, &s, &c);
    float lx[4] = {-0.5f * w,  0.5f * w, 0.5f * w, -0.5f * w};
    float ly[4] = {-0.5f * h, -0.5f * h, 0.5f * h,  0.5f * h};
    #pragma unroll
    for (int k = 0; k < 4; k++) {
        X[k] = cx + lx[k] * c - ly[k] * s;
        Y[k] = cy + lx[k] * s + ly[k] * c;
    }
}

// ---------------- kernel 1: assign blocks ∥ focal-neg blocks --------------
__global__ __launch_bounds__(ABLK)
void mega_kernel(const float* __restrict__ anchors,
                 const float* __restrict__ gt_boxes,
                 const int*   __restrict__ gt_labels,
                 const float* __restrict__ logits,
                 int N, int G, int C, int ablocks, int fblocks)
{
    int b = blockIdx.y;
    int t = threadIdx.x;

    if ((int)blockIdx.x >= ablocks) {
        // ---- focal role: sum fl_neg over all logits (assignment-independent)
        int fb     = blockIdx.x - ablocks;
        int gtid   = fb * ABLK + t;
        int stride = fblocks * ABLK;
        int E  = N * C;
        int E4 = E >> 2;
        const float4* lp4 = (const float4*)(logits + (size_t)b * E);

        float acc = 0.0f;
        for (int q = gtid; q < E4; q += stride) {
            float4 v = lp4[q];
            acc += fl_neg(v.x) + fl_neg(v.y) + fl_neg(v.z) + fl_neg(v.w);
        }
        for (int e = (E4 << 2) + gtid; e < E; e += stride)
            acc += fl_neg(logits[(size_t)b * E + e]);

        __shared__ float sa[ABLK];
        sa[t] = acc;
        __syncthreads();
        for (int s = ABLK / 2; s > 0; s >>= 1) {
            if (t < s) sa[t] += sa[t + s];
            __syncthreads();
        }
        if (t == 0) g_part[b * MAXPB + fb] = (double)sa[0];
        return;
    }

    // ---- assign role ----
    int i0 = blockIdx.x * ABLK;
    int i  = i0 + t;

    __shared__ float sgx[MAXG][4], sgy[MAXG][4];   // GT corners (absolute)
    __shared__ float sgb[MAXG][5];
    __shared__ float sg_sz[MAXG];
    __shared__ float sg_area[MAXG];
    __shared__ int   s_gl[MAXG];
    __shared__ unsigned long long s_best[MAXG];    // per-GT best anchor
    __shared__ unsigned long long s_bestA[ABLK];   // per-anchor best GT
    __shared__ float s_anc[ABLK][5];
    __shared__ float s_acx[ABLK][4], s_acy[ABLK][4]; // anchor corners, centered
    __shared__ unsigned short s_q[ABLK * 16];
    __shared__ int   s_qn;
    __shared__ int   s_last;

    if (t == 0) { s_qn = 0; s_last = 0; }
    if (t < G) {
        const float* gb = gt_boxes + (size_t)(b * G + t) * 5;
        float w = gb[2], h = gb[3];
        #pragma unroll
        for (int k = 0; k < 5; k++) sgb[t][k] = gb[k];
        sg_sz[t]   = fmaxf(w, h);
        sg_area[t] = w * h;
        s_gl[t]    = gt_labels[b * G + t];
        make_corners_f(gb[0], gb[1], w, h, gb[4], sgx[t], sgy[t]);
        s_best[t] = 0ULL;
    }
    s_bestA[t] = 0ULL;
    if (i < N) {
        const float* ab = anchors + (size_t)i * 5;
        #pragma unroll
        for (int k = 0; k < 5; k++) s_anc[t][k] = ab[k];
        // corners relative to anchor center (translation-invariant area)
        make_corners_f(0.0f, 0.0f, ab[2], ab[3], ab[4], s_acx[t], s_acy[t]);
    }
    __syncthreads();

    // phase 1: gate, build pair queue
    if (i < N) {
        float ax = s_anc[t][0], ay = s_anc[t][1];
        float a_sz = fmaxf(s_anc[t][2], s_anc[t][3]);
        for (int j = 0; j < G; j++) {
            float dx = ax - sgb[j][0];
            float dy = ay - sgb[j][1];
            float gate = (a_sz + sg_sz[j]) * 0.7f;
            if (sqrtf(dx * dx + dy * dy) < gate) {
                int p = atomicAdd(&s_qn, 1);
                s_q[p] = (unsigned short)((t << 5) | j);
            }
        }
    }
    __syncthreads();

    // phase 2: drain queue; register-resident edge-interval intersection
    int qn = s_qn;
    for (int q = t; q < qn; q += ABLK) {
        int e  = s_q[q];
        int li = e >> 5;
        int j  = e & 31;

        float axc = s_anc[li][0], ayc = s_anc[li][1];
        float pa[4], qa[4], pb[4], qb[4];
        #pragma unroll
        for (int k = 0; k < 4; k++) {
            pa[k] = s_acx[li][k];          // anchor corners (centered)
            qa[k] = s_acy[li][k];
            pb[k] = sgx[j][k] - axc;       // GT corners, same frame
            qb[k] = sgy[j][k] - ayc;
        }

        float cs = arcs_cross_sum(pa, qa, pb, qb)
                 + arcs_cross_sum(pb, qb, pa, qa);
        float inter = 0.5f * cs;

        float a_area = s_anc[li][2] * s_anc[li][3];
        float iou = inter / (a_area + sg_area[j] - inter + 1e-8f);
        if (iou > 0.0f) {
            // per-anchor argmax, tie -> smaller j (first occurrence)
            unsigned long long ka =
                ((unsigned long long)__float_as_uint(iou) << 32)
                | (unsigned long long)(unsigned)(MAXG - 1 - j);
            atomicMax(&s_bestA[li], ka);
            // per-GT argmax over anchors, tie -> smaller anchor index
            unsigned long long kg =
                ((unsigned long long)__float_as_uint(iou) << 32)
                | (unsigned long long)(0xFFFFFFFFu - (unsigned)(i0 + li));
            atomicMax(&s_best[j], kg);
        }
    }
    __syncthreads();

    // phase 3: unpack per-anchor best, thresholds
    if (i < N) {
        unsigned long long ka = s_bestA[t];
        float best_iou = __uint_as_float((unsigned)(ka >> 32));
        int   best_j   = MAXG - 1 - (int)(ka & 31u);
        int lab;
        if (best_iou >= 0.5f) {
            lab = s_gl[best_j] + 1;
            #pragma unroll
            for (int k = 0; k < 5; k++)
                g_mg[(size_t)(b * MAXN + i) * 5 + k] = sgb[best_j][k];
        } else {
            lab = (best_iou < 0.4f) ? 0 : -1;
        }
        g_lab[b * MAXN + i] = lab;
    }
    __syncthreads();

    if (t < G && s_best[t] != 0ULL)
        atomicMax(&g_best[b * MAXG + t], s_best[t]);

    __syncthreads();
    if (t == 0) {
        __threadfence();
        int v = atomicAdd(&g_cnt1[b], 1);
        if (v == ablocks - 1) s_last = 1;
    }
    __syncthreads();
    if (s_last && t == 0) {
        __threadfence();
        for (int j = 0; j < G; j++) {
            unsigned long long key = g_best[b * MAXG + j];
            g_best[b * MAXG + j] = 0ULL;
            if ((key >> 32) != 0ULL) {
                int bi = (int)(0xFFFFFFFFu - (unsigned)(key & 0xFFFFFFFFu));
                int gl = s_gl[j] + 1;
                if (g_lab[b * MAXN + bi] != gl) {
                    g_lab[b * MAXN + bi] = gl;
                    #pragma unroll
                    for (int k = 0; k < 5; k++)
                        g_mg[(size_t)(b * MAXN + bi) * 5 + k] = sgb[j][k];
                }
            }
        }
        g_cnt1[b] = 0;
    }
}

// ---------------- kernel 2: corrections + reg + final reduce --------------
__global__ void finish_kernel(const float* __restrict__ logits,
                              const float* __restrict__ box_reg,
                              const float* __restrict__ anchors,
                              float* __restrict__ out,
                              int N, int C, int B, int fblocks)
{
    int b = blockIdx.y;
    int t = threadIdx.x;
    int gtid   = blockIdx.x * KTHR + t;
    int stride = gridDim.x * KTHR;

    float cf = 0.0f, rl = 0.0f, np = 0.0f;

    for (int i = gtid; i < N; i += stride) {
        int lab = g_lab[b * MAXN + i];
        if (lab < 0) {
            const float* lp = logits + ((size_t)b * N + i) * (size_t)C;
            float s = 0.0f;
            for (int c = 0; c < C; c++) s += fl_neg(lp[c]);
            cf -= s;
        } else if (lab > 0) {
            float x = logits[((size_t)b * N + i) * (size_t)C + (lab - 1)];
            cf += fl_pos(x) - fl_neg(x);
            np += 1.0f;
            const float* ab = anchors + (size_t)i * 5;
            const float* mg = &g_mg[(size_t)(b * MAXN + i) * 5];
            const float* br = box_reg + ((size_t)b * N + i) * 5;
            float dlt[5];
            dlt[0] = (mg[0] - ab[0]) / ab[2];
            dlt[1] = (mg[1] - ab[1]) / ab[3];
            dlt[2] = logf(mg[2] / ab[2]);
            dlt[3] = logf(mg[3] / ab[3]);
            dlt[4] = jrem180(mg[4] - ab[4] + 90.0f) - 90.0f;
            float l = 0.0f;
            #pragma unroll
            for (int k = 0; k < 4; k++) {
                float d = fabsf(br[k] - dlt[k]);
                l += (d < 1.0f) ? 0.5f * d * d : d - 0.5f;
            }
            float da = fabsf(jrem180(br[4] - dlt[4] + 90.0f) - 90.0f);
            l += (da < 1.0f) ? 0.5f * da * da : da - 0.5f;
            rl += l;
        }
    }

    __shared__ float sf[KTHR], sr[KTHR], sn[KTHR];
    __shared__ int   s_last;
    if (t == 0) s_last = 0;
    sf[t] = cf; sr[t] = rl; sn[t] = np;
    __syncthreads();
    for (int s = KTHR / 2; s > 0; s >>= 1) {
        if (t < s) { sf[t] += sf[t + s]; sr[t] += sr[t + s]; sn[t] += sn[t + s]; }
        __syncthreads();
    }
    if (t == 0) {
        size_t o = (size_t)(b * KBLK + blockIdx.x) * 3;
        g_part2[o + 0] = (double)sf[0];
        g_part2[o + 1] = (double)sr[0];
        g_part2[o + 2] = (double)sn[0];
        __threadfence();
        int total = (int)(gridDim.x * gridDim.y);
        int v = atomicAdd(&g_cnt2, 1);
        if (v == total - 1) s_last = 1;
    }
    __syncthreads();

    if (s_last) {
        if (t == 0) __threadfence();
        __syncthreads();
        __shared__ double df[KTHR], dr[KTHR], dn[KTHR];
        double cls_m = 0.0, reg_m = 0.0;
        for (int bb = 0; bb < B; bb++) {
            double f = 0.0, r = 0.0, n = 0.0;
            for (int k = t; k < fblocks; k += KTHR)
                f += g_part[bb * MAXPB + k];
            for (int k = t; k < KBLK; k += KTHR) {
                size_t o = (size_t)(bb * KBLK + k) * 3;
                f += g_part2[o + 0];
                r += g_part2[o + 1];
                n += g_part2[o + 2];
            }
            df[t] = f; dr[t] = r; dn[t] = n;
            __syncthreads();
            for (int s = KTHR / 2; s > 0; s >>= 1) {
                if (t < s) { df[t] += df[t+s]; dr[t] += dr[t+s]; dn[t] += dn[t+s]; }
                __syncthreads();
            }
            if (t == 0) {
                double npos = (dn[0] < 1.0) ? 1.0 : dn[0];
                cls_m += df[0] / npos;
                reg_m += dr[0] / npos;
            }
            __syncthreads();
        }
        if (t == 0) {
            cls_m /= (double)B;
            reg_m /= (double)B;
            out[0] = (float)(cls_m + reg_m);
            out[1] = (float)cls_m;
            out[2] = (float)reg_m;
            g_cnt2 = 0;
        }
    }
}

// ---------------- launch ----------------
extern "C" void kernel_launch(void* const* d_in, const int* in_sizes, int n_in,
                              void* d_out, int out_size)
{
    const float* logits  = (const float*)d_in[0];
    const float* breg    = (const float*)d_in[1];
    const float* anchors = (const float*)d_in[2];
    const float* gtb     = (const float*)d_in[3];
    const int*   gtl     = (const int*)d_in[4];

    int N = in_sizes[2] / 5;
    int B = in_sizes[1] / (5 * N);
    int C = in_sizes[0] / (B * N);
    int G = in_sizes[4] / B;

    int ablocks = (N + ABLK - 1) / ABLK;
    int fblocks = FBLKS;

    dim3 mg(ablocks + fblocks, B);
    mega_kernel<<<mg, ABLK>>>(anchors, gtb, gtl, logits, N, G, C,
                              ablocks, fblocks);

    dim3 fg(KBLK, B);
    finish_kernel<<<fg, KTHR>>>(logits, breg, anchors, (float*)d_out,
                                N, C, B, fblocks);
}

// round 14
// speedup vs baseline: 1.9270x; 1.0827x over previous
#include <cuda_runtime.h>
#include <math.h>

#define MAXB   4
#define MAXN   16384
#define MAXG   32
#define MAXPB  256
#define CBLK   32        // correction blocks per image
#define ABLK   128
#define FBLKS  128

#ifndef M_PI
#define M_PI 3.14159265358979323846
#endif

// ---------------- device scratch (no allocations allowed) ----------------
__device__ int                  g_lab[MAXB * MAXN];
__device__ float                g_mg[MAXB * MAXN * 5];
__device__ unsigned long long   g_best[MAXB * MAXG];
__device__ double               g_part[MAXB * MAXPB];      // focal-neg partials
__device__ double               g_part2[MAXB * CBLK * 3];  // correction partials
__device__ int                  g_cnt1[MAXB];
__device__ int                  g_cnt2;
__device__ volatile int         g_done[MAXB];

// ---------------- helpers ----------------
__device__ __forceinline__ float jrem180(float x) {
    float r = fmodf(x, 180.0f);
    if (r < 0.0f) r += 180.0f;
    return r;
}

__device__ __forceinline__ float fl_neg(float x) {
    float e     = __expf(-x);
    float denom = 1.0f + e;
    float L     = __logf(denom);
    float inv   = __fdividef(1.0f, denom);
    return 0.75f * inv * inv * (L + x);
}

__device__ __forceinline__ float fl_pos(float x) {
    float e     = __expf(-x);
    float denom = 1.0f + e;
    float L     = __logf(denom);
    float inv   = __fdividef(1.0f, denom);
    float om    = e * inv;
    return 0.25f * om * om * L;
}

// register-resident convex quad intersection (edge param-interval form)
__device__ __forceinline__ float arcs_cross_sum(const float* Px, const float* Py,
                                                const float* Qx, const float* Qy)
{
    float acc = 0.0f;
    #pragma unroll
    for (int i = 0; i < 4; i++) {
        int i1 = (i + 1) & 3;
        float ax = Px[i], ay = Py[i];
        float rx = Px[i1] - ax, ry = Py[i1] - ay;
        float p = 0.0f, q = 1.0f;
        float r = 1.0f, s = 1.0f;
        bool empty = false;
        #pragma unroll
        for (int j = 0; j < 4; j++) {
            int j1 = (j + 1) & 3;
            float ex = Qx[j1] - Qx[j], ey = Qy[j1] - Qy[j];
            float d0 = ex * (ay - Qy[j]) - ey * (ax - Qx[j]);
            float d1 = d0 + ex * ry - ey * rx;
            if (d0 < 0.0f) {
                if (d1 < 0.0f) {
                    empty = true;
                } else {
                    float n = -d0, den = d1 - d0;
                    if (n * q > p * den) { p = n; q = den; }
                }
            } else if (d1 < 0.0f) {
                float n = d0, den = d0 - d1;
                if (n * s < r * den) { r = n; s = den; }
            }
        }
        float num = r * q - p * s;
        if (!empty && num > 0.0f)
            acc += num * __fdividef(ax * ry - rx * ay, s * q);
    }
    return acc;
}

__device__ __forceinline__ void make_corners_f(float cx, float cy, float w,
                                               float h, float th,
                                               float* X, float* Y)
{
    float r = th * (float)(M_PI / 180.0);
    float s, c;
    __sincosf(r, &s, &c);
    float lx[4] = {-0.5f * w,  0.5f * w, 0.5f * w, -0.5f * w};
    float ly[4] = {-0.5f * h, -0.5f * h, 0.5f * h,  0.5f * h};
    #pragma unroll
    for (int k = 0; k < 4; k++) {
        X[k] = cx + lx[k] * c - ly[k] * s;
        Y[k] = cy + lx[k] * s + ly[k] * c;
    }
}

// grid-wide finalize (runs in the overall-last block)
__device__ void finalize(float* out, int B, int fblocks)
{
    int t = threadIdx.x;
    __shared__ double df[ABLK], dr[ABLK], dn[ABLK];
    double cls_m = 0.0, reg_m = 0.0;
    for (int bb = 0; bb < B; bb++) {
        double f = 0.0, r = 0.0, n = 0.0;
        for (int k = t; k < fblocks; k += ABLK)
            f += g_part[bb * MAXPB + k];
        for (int k = t; k < CBLK; k += ABLK) {
            size_t o = (size_t)(bb * CBLK + k) * 3;
            f += g_part2[o + 0];
            r += g_part2[o + 1];
            n += g_part2[o + 2];
        }
        df[t] = f; dr[t] = r; dn[t] = n;
        __syncthreads();
        for (int s = ABLK / 2; s > 0; s >>= 1) {
            if (t < s) { df[t] += df[t+s]; dr[t] += dr[t+s]; dn[t] += dn[t+s]; }
            __syncthreads();
        }
        if (t == 0) {
            double npos = (dn[0] < 1.0) ? 1.0 : dn[0];
            cls_m += df[0] / npos;
            reg_m += dr[0] / npos;
        }
        __syncthreads();
    }
    if (t == 0) {
        cls_m /= (double)B;
        reg_m /= (double)B;
        out[0] = (float)(cls_m + reg_m);
        out[1] = (float)cls_m;
        out[2] = (float)reg_m;
        for (int bb = 0; bb < B; bb++) g_done[bb] = 0;
        g_cnt2 = 0;
    }
}

// ---------------- the single kernel ----------------
__global__ __launch_bounds__(ABLK)
void mega_kernel(const float* __restrict__ anchors,
                 const float* __restrict__ gt_boxes,
                 const int*   __restrict__ gt_labels,
                 const float* __restrict__ logits,
                 const float* __restrict__ box_reg,
                 float* __restrict__ out,
                 int N, int G, int C, int B, int ablocks, int fblocks)
{
    int b = blockIdx.y;
    int t = threadIdx.x;
    int total_blocks = (int)(gridDim.x * gridDim.y);

    __shared__ int s_final;
    if (t == 0) s_final = 0;

    // ================= role 2: focal-neg =================
    if ((int)blockIdx.x >= ablocks && (int)blockIdx.x < ablocks + fblocks) {
        int fb     = blockIdx.x - ablocks;
        int gtid   = fb * ABLK + t;
        int stride = fblocks * ABLK;
        int E  = N * C;
        int E4 = E >> 2;
        const float4* lp4 = (const float4*)(logits + (size_t)b * E);

        float acc = 0.0f;
        for (int q = gtid; q < E4; q += stride) {
            float4 v = lp4[q];
            acc += fl_neg(v.x) + fl_neg(v.y) + fl_neg(v.z) + fl_neg(v.w);
        }
        for (int e = (E4 << 2) + gtid; e < E; e += stride)
            acc += fl_neg(logits[(size_t)b * E + e]);

        __shared__ float sa[ABLK];
        sa[t] = acc;
        __syncthreads();
        for (int s = ABLK / 2; s > 0; s >>= 1) {
            if (t < s) sa[t] += sa[t + s];
            __syncthreads();
        }
        if (t == 0) {
            g_part[b * MAXPB + fb] = (double)sa[0];
            __threadfence();
            int v = atomicAdd(&g_cnt2, 1);
            if (v == total_blocks - 1) s_final = 1;
        }
        __syncthreads();
        if (s_final) finalize(out, B, fblocks);
        return;
    }

    // ================= role 3: corrections (spin on force-done) ==========
    if ((int)blockIdx.x >= ablocks + fblocks) {
        int cb = blockIdx.x - ablocks - fblocks;
        if (t == 0) {
            while (g_done[b] == 0) __nanosleep(200);
        }
        __syncthreads();
        __threadfence();   // acquire labels/mg

        int gtid   = cb * ABLK + t;
        int stride = CBLK * ABLK;
        float cf = 0.0f, rl = 0.0f, np = 0.0f;

        for (int i = gtid; i < N; i += stride) {
            int lab = g_lab[b * MAXN + i];
            if (lab < 0) {
                const float* lp = logits + ((size_t)b * N + i) * (size_t)C;
                float s = 0.0f;
                for (int c = 0; c < C; c++) s += fl_neg(lp[c]);
                cf -= s;
            } else if (lab > 0) {
                float x = logits[((size_t)b * N + i) * (size_t)C + (lab - 1)];
                cf += fl_pos(x) - fl_neg(x);
                np += 1.0f;
                const float* ab = anchors + (size_t)i * 5;
                const float* mg = &g_mg[(size_t)(b * MAXN + i) * 5];
                const float* br = box_reg + ((size_t)b * N + i) * 5;
                float dlt[5];
                dlt[0] = (mg[0] - ab[0]) / ab[2];
                dlt[1] = (mg[1] - ab[1]) / ab[3];
                dlt[2] = logf(mg[2] / ab[2]);
                dlt[3] = logf(mg[3] / ab[3]);
                dlt[4] = jrem180(mg[4] - ab[4] + 90.0f) - 90.0f;
                float l = 0.0f;
                #pragma unroll
                for (int k = 0; k < 4; k++) {
                    float d = fabsf(br[k] - dlt[k]);
                    l += (d < 1.0f) ? 0.5f * d * d : d - 0.5f;
                }
                float da = fabsf(jrem180(br[4] - dlt[4] + 90.0f) - 90.0f);
                l += (da < 1.0f) ? 0.5f * da * da : da - 0.5f;
                rl += l;
            }
        }

        __shared__ float sf[ABLK], sr[ABLK], sn[ABLK];
        sf[t] = cf; sr[t] = rl; sn[t] = np;
        __syncthreads();
        for (int s = ABLK / 2; s > 0; s >>= 1) {
            if (t < s) { sf[t] += sf[t+s]; sr[t] += sr[t+s]; sn[t] += sn[t+s]; }
            __syncthreads();
        }
        if (t == 0) {
            size_t o = (size_t)(b * CBLK + cb) * 3;
            g_part2[o + 0] = (double)sf[0];
            g_part2[o + 1] = (double)sr[0];
            g_part2[o + 2] = (double)sn[0];
            __threadfence();
            int v = atomicAdd(&g_cnt2, 1);
            if (v == total_blocks - 1) s_final = 1;
        }
        __syncthreads();
        if (s_final) finalize(out, B, fblocks);
        return;
    }

    // ================= role 1: assign =================
    int i0 = blockIdx.x * ABLK;
    int i  = i0 + t;

    __shared__ float sgx[MAXG][4], sgy[MAXG][4];
    __shared__ float sgb[MAXG][5];
    __shared__ float sg_sz[MAXG];
    __shared__ float sg_area[MAXG];
    __shared__ int   s_gl[MAXG];
    __shared__ unsigned long long s_best[MAXG];
    __shared__ unsigned long long s_bestA[ABLK];
    __shared__ float s_anc[ABLK][5];
    __shared__ float s_acx[ABLK][4], s_acy[ABLK][4];
    __shared__ unsigned short s_q[ABLK * 16];
    __shared__ int   s_qn;
    __shared__ int   s_last;
    // force-tail staging
    __shared__ int   s_bi[MAXG], s_labv[MAXG], s_has[MAXG];

    if (t == 0) { s_qn = 0; s_last = 0; }
    if (t < G) {
        const float* gb = gt_boxes + (size_t)(b * G + t) * 5;
        float w = gb[2], h = gb[3];
        #pragma unroll
        for (int k = 0; k < 5; k++) sgb[t][k] = gb[k];
        sg_sz[t]   = fmaxf(w, h);
        sg_area[t] = w * h;
        s_gl[t]    = gt_labels[b * G + t];
        make_corners_f(gb[0], gb[1], w, h, gb[4], sgx[t], sgy[t]);
        s_best[t] = 0ULL;
    }
    s_bestA[t] = 0ULL;
    if (i < N) {
        const float* ab = anchors + (size_t)i * 5;
        #pragma unroll
        for (int k = 0; k < 5; k++) s_anc[t][k] = ab[k];
        make_corners_f(0.0f, 0.0f, ab[2], ab[3], ab[4], s_acx[t], s_acy[t]);
    }
    __syncthreads();

    // phase 1: gate -> queue
    if (i < N) {
        float ax = s_anc[t][0], ay = s_anc[t][1];
        float a_sz = fmaxf(s_anc[t][2], s_anc[t][3]);
        for (int j = 0; j < G; j++) {
            float dx = ax - sgb[j][0];
            float dy = ay - sgb[j][1];
            float gate = (a_sz + sg_sz[j]) * 0.7f;
            if (sqrtf(dx * dx + dy * dy) < gate) {
                int p = atomicAdd(&s_qn, 1);
                s_q[p] = (unsigned short)((t << 5) | j);
            }
        }
    }
    __syncthreads();

    // phase 2: drain queue
    int qn = s_qn;
    for (int q = t; q < qn; q += ABLK) {
        int e  = s_q[q];
        int li = e >> 5;
        int j  = e & 31;

        float axc = s_anc[li][0], ayc = s_anc[li][1];
        float pa[4], qa[4], pb[4], qb[4];
        #pragma unroll
        for (int k = 0; k < 4; k++) {
            pa[k] = s_acx[li][k];
            qa[k] = s_acy[li][k];
            pb[k] = sgx[j][k] - axc;
            qb[k] = sgy[j][k] - ayc;
        }
        float inter = 0.5f * (arcs_cross_sum(pa, qa, pb, qb)
                            + arcs_cross_sum(pb, qb, pa, qa));
        float a_area = s_anc[li][2] * s_anc[li][3];
        float iou = inter / (a_area + sg_area[j] - inter + 1e-8f);
        if (iou > 0.0f) {
            unsigned long long ka =
                ((unsigned long long)__float_as_uint(iou) << 32)
                | (unsigned long long)(unsigned)(MAXG - 1 - j);
            atomicMax(&s_bestA[li], ka);
            unsigned long long kg =
                ((unsigned long long)__float_as_uint(iou) << 32)
                | (unsigned long long)(0xFFFFFFFFu - (unsigned)(i0 + li));
            atomicMax(&s_best[j], kg);
        }
    }
    __syncthreads();

    // phase 3: labels
    if (i < N) {
        unsigned long long ka = s_bestA[t];
        float best_iou = __uint_as_float((unsigned)(ka >> 32));
        int   best_j   = MAXG - 1 - (int)(ka & 31u);
        int lab;
        if (best_iou >= 0.5f) {
            lab = s_gl[best_j] + 1;
            #pragma unroll
            for (int k = 0; k < 5; k++)
                g_mg[(size_t)(b * MAXN + i) * 5 + k] = sgb[best_j][k];
        } else {
            lab = (best_iou < 0.4f) ? 0 : -1;
        }
        g_lab[b * MAXN + i] = lab;
    }
    __syncthreads();

    if (t < G && s_best[t] != 0ULL)
        atomicMax(&g_best[b * MAXG + t], s_best[t]);

    __syncthreads();
    if (t == 0) {
        __threadfence();
        int v = atomicAdd(&g_cnt1[b], 1);
        if (v == ablocks - 1) s_last = 1;
    }
    __syncthreads();

    // force-match tail: parallel prefetch, thread-0 logic, async stores
    if (s_last) {
        if (t == 0) __threadfence();  // acquire all assign blocks' writes
        __syncthreads();
        if (t < G) {
            unsigned long long key = g_best[b * MAXG + t];
            g_best[b * MAXG + t] = 0ULL;
            int has = (key >> 32) != 0ULL;
            s_has[t] = has;
            int bi = has ? (int)(0xFFFFFFFFu - (unsigned)(key & 0xFFFFFFFFu)) : 0;
            s_bi[t] = bi;
            s_labv[t] = has ? g_lab[b * MAXN + bi] : 0;
        }
        __syncthreads();
        if (t == 0) {
            for (int j = 0; j < G; j++) {
                if (s_has[j]) {
                    int bi = s_bi[j];
                    int gl = s_gl[j] + 1;
                    if (s_labv[j] != gl) {
                        g_lab[b * MAXN + bi] = gl;
                        float* mgp = &g_mg[(size_t)(b * MAXN + bi) * 5];
                        #pragma unroll
                        for (int k = 0; k < 5; k++) mgp[k] = sgb[j][k];
                        // propagate to later GTs sharing this anchor
                        for (int j2 = j + 1; j2 < G; j2++)
                            if (s_has[j2] && s_bi[j2] == bi) s_labv[j2] = gl;
                    }
                }
            }
            g_cnt1[b] = 0;
            __threadfence();       // release labels/mg before raising flag
            g_done[b] = 1;
        }
    }
    __syncthreads();

    if (t == 0) {
        __threadfence();
        int v = atomicAdd(&g_cnt2, 1);
        if (v == total_blocks - 1) s_final = 1;
    }
    __syncthreads();
    if (s_final) finalize(out, B, fblocks);
}

// ---------------- launch ----------------
extern "C" void kernel_launch(void* const* d_in, const int* in_sizes, int n_in,
                              void* d_out, int out_size)
{
    const float* logits  = (const float*)d_in[0];
    const float* breg    = (const float*)d_in[1];
    const float* anchors = (const float*)d_in[2];
    const float* gtb     = (const float*)d_in[3];
    const int*   gtl     = (const int*)d_in[4];

    int N = in_sizes[2] / 5;
    int B = in_sizes[1] / (5 * N);
    int C = in_sizes[0] / (B * N);
    int G = in_sizes[4] / B;

    int ablocks = (N + ABLK - 1) / ABLK;
    int fblocks = FBLKS;

    dim3 mg(ablocks + fblocks + CBLK, B);
    mega_kernel<<<mg, ABLK>>>(anchors, gtb, gtl, logits, breg,
                              (float*)d_out, N, G, C, B, ablocks, fblocks);
}

// round 15
// speedup vs baseline: 2.1149x; 1.0975x over previous
#include <cuda_runtime.h>
#include <math.h>

#define MAXB   4
#define MAXN   16384
#define MAXG   32
#define MAXPB  256
#define ABLK   128
#define FBLKS  128       // focal+correction blocks per image

#ifndef M_PI
#define M_PI 3.14159265358979323846
#endif

// ---------------- device scratch (no allocations allowed) ----------------
__device__ int                  g_lab[MAXB * MAXN];
__device__ float                g_mg[MAXB * MAXN * 5];
__device__ unsigned long long   g_best[MAXB * MAXG];
__device__ double               g_part[MAXB * MAXPB];       // focal-neg partials
__device__ double               g_part2[MAXB * MAXPB * 3];  // correction partials
__device__ int                  g_cnt1[MAXB];
__device__ int                  g_cnt2;
__device__ volatile int         g_done[MAXB];

// ---------------- helpers ----------------
__device__ __forceinline__ float jrem180(float x) {
    float r = fmodf(x, 180.0f);
    if (r < 0.0f) r += 180.0f;
    return r;
}

__device__ __forceinline__ float fl_neg(float x) {
    float e     = __expf(-x);
    float denom = 1.0f + e;
    float L     = __logf(denom);
    float inv   = __fdividef(1.0f, denom);
    return 0.75f * inv * inv * (L + x);
}

__device__ __forceinline__ float fl_pos(float x) {
    float e     = __expf(-x);
    float denom = 1.0f + e;
    float L     = __logf(denom);
    float inv   = __fdividef(1.0f, denom);
    float om    = e * inv;
    return 0.25f * om * om * L;
}

// register-resident convex quad intersection (edge param-interval form)
__device__ __forceinline__ float arcs_cross_sum(const float* Px, const float* Py,
                                                const float* Qx, const float* Qy)
{
    float acc = 0.0f;
    #pragma unroll
    for (int i = 0; i < 4; i++) {
        int i1 = (i + 1) & 3;
        float ax = Px[i], ay = Py[i];
        float rx = Px[i1] - ax, ry = Py[i1] - ay;
        float p = 0.0f, q = 1.0f;
        float r = 1.0f, s = 1.0f;
        bool empty = false;
        #pragma unroll
        for (int j = 0; j < 4; j++) {
            int j1 = (j + 1) & 3;
            float ex = Qx[j1] - Qx[j], ey = Qy[j1] - Qy[j];
            float d0 = ex * (ay - Qy[j]) - ey * (ax - Qx[j]);
            float d1 = d0 + ex * ry - ey * rx;
            if (d0 < 0.0f) {
                if (d1 < 0.0f) {
                    empty = true;
                } else {
                    float n = -d0, den = d1 - d0;
                    if (n * q > p * den) { p = n; q = den; }
                }
            } else if (d1 < 0.0f) {
                float n = d0, den = d0 - d1;
                if (n * s < r * den) { r = n; s = den; }
            }
        }
        float num = r * q - p * s;
        if (!empty && num > 0.0f)
            acc += num * __fdividef(ax * ry - rx * ay, s * q);
    }
    return acc;
}

__device__ __forceinline__ void make_corners_f(float cx, float cy, float w,
                                               float h, float th,
                                               float* X, float* Y)
{
    float r = th * (float)(M_PI / 180.0);
    float s, c;
    __sincosf(r, &s, &c);
    float lx[4] = {-0.5f * w,  0.5f * w, 0.5f * w, -0.5f * w};
    float ly[4] = {-0.5f * h, -0.5f * h, 0.5f * h,  0.5f * h};
    #pragma unroll
    for (int k = 0; k < 4; k++) {
        X[k] = cx + lx[k] * c - ly[k] * s;
        Y[k] = cy + lx[k] * s + ly[k] * c;
    }
}

// grid-wide finalize (runs in the overall-last block)
__device__ void finalize(float* out, int B, int fblocks)
{
    int t = threadIdx.x;
    __shared__ double df[ABLK], dr[ABLK], dn[ABLK];
    double cls_m = 0.0, reg_m = 0.0;
    for (int bb = 0; bb < B; bb++) {
        double f = 0.0, r = 0.0, n = 0.0;
        for (int k = t; k < fblocks; k += ABLK) {
            f += g_part[bb * MAXPB + k];
            size_t o = (size_t)(bb * MAXPB + k) * 3;
            f += g_part2[o + 0];
            r += g_part2[o + 1];
            n += g_part2[o + 2];
        }
        df[t] = f; dr[t] = r; dn[t] = n;
        __syncthreads();
        for (int s = ABLK / 2; s > 0; s >>= 1) {
            if (t < s) { df[t] += df[t+s]; dr[t] += dr[t+s]; dn[t] += dn[t+s]; }
            __syncthreads();
        }
        if (t == 0) {
            double npos = (dn[0] < 1.0) ? 1.0 : dn[0];
            cls_m += df[0] / npos;
            reg_m += dr[0] / npos;
        }
        __syncthreads();
    }
    if (t == 0) {
        cls_m /= (double)B;
        reg_m /= (double)B;
        out[0] = (float)(cls_m + reg_m);
        out[1] = (float)cls_m;
        out[2] = (float)reg_m;
        for (int bb = 0; bb < B; bb++) g_done[bb] = 0;
        g_cnt2 = 0;
    }
}

// ---------------- the single kernel ----------------
__global__ __launch_bounds__(ABLK)
void mega_kernel(const float* __restrict__ anchors,
                 const float* __restrict__ gt_boxes,
                 const int*   __restrict__ gt_labels,
                 const float* __restrict__ logits,
                 const float* __restrict__ box_reg,
                 float* __restrict__ out,
                 int N, int G, int C, int B, int ablocks, int fblocks)
{
    int b = blockIdx.y;
    int t = threadIdx.x;
    int total_blocks = (int)(gridDim.x * gridDim.y);

    __shared__ int s_final;
    if (t == 0) s_final = 0;

    // ============ role 2: focal-neg, then corrections after force-done ====
    if ((int)blockIdx.x >= ablocks) {
        int fb     = blockIdx.x - ablocks;
        int gtid   = fb * ABLK + t;
        int stride = fblocks * ABLK;
        int E  = N * C;
        int E4 = E >> 2;
        const float4* lp4 = (const float4*)(logits + (size_t)b * E);

        float acc = 0.0f;
        for (int q = gtid; q < E4; q += stride) {
            float4 v = lp4[q];
            acc += fl_neg(v.x) + fl_neg(v.y) + fl_neg(v.z) + fl_neg(v.w);
        }
        for (int e = (E4 << 2) + gtid; e < E; e += stride)
            acc += fl_neg(logits[(size_t)b * E + e]);

        __shared__ float sa[ABLK];
        sa[t] = acc;
        __syncthreads();
        for (int s = ABLK / 2; s > 0; s >>= 1) {
            if (t < s) sa[t] += sa[t + s];
            __syncthreads();
        }
        if (t == 0) g_part[b * MAXPB + fb] = (double)sa[0];

        // wait for this image's force-match, then corrections
        if (t == 0) {
            while (g_done[b] == 0) __nanosleep(100);
        }
        __syncthreads();
        __threadfence();   // acquire labels/mg

        float cf = 0.0f, rl = 0.0f, np = 0.0f;
        for (int i = gtid; i < N; i += stride) {
            int lab = g_lab[b * MAXN + i];
            if (lab < 0) {
                const float* lp = logits + ((size_t)b * N + i) * (size_t)C;
                float s = 0.0f;
                for (int c = 0; c < C; c++) s += fl_neg(lp[c]);
                cf -= s;
            } else if (lab > 0) {
                float x = logits[((size_t)b * N + i) * (size_t)C + (lab - 1)];
                cf += fl_pos(x) - fl_neg(x);
                np += 1.0f;
                const float* ab = anchors + (size_t)i * 5;
                const float* mg = &g_mg[(size_t)(b * MAXN + i) * 5];
                const float* br = box_reg + ((size_t)b * N + i) * 5;
                float dlt[5];
                dlt[0] = (mg[0] - ab[0]) / ab[2];
                dlt[1] = (mg[1] - ab[1]) / ab[3];
                dlt[2] = logf(mg[2] / ab[2]);
                dlt[3] = logf(mg[3] / ab[3]);
                dlt[4] = jrem180(mg[4] - ab[4] + 90.0f) - 90.0f;
                float l = 0.0f;
                #pragma unroll
                for (int k = 0; k < 4; k++) {
                    float d = fabsf(br[k] - dlt[k]);
                    l += (d < 1.0f) ? 0.5f * d * d : d - 0.5f;
                }
                float da = fabsf(jrem180(br[4] - dlt[4] + 90.0f) - 90.0f);
                l += (da < 1.0f) ? 0.5f * da * da : da - 0.5f;
                rl += l;
            }
        }

        __shared__ float sf[ABLK], sr[ABLK], sn[ABLK];
        sf[t] = cf; sr[t] = rl; sn[t] = np;
        __syncthreads();
        for (int s = ABLK / 2; s > 0; s >>= 1) {
            if (t < s) { sf[t] += sf[t+s]; sr[t] += sr[t+s]; sn[t] += sn[t+s]; }
            __syncthreads();
        }
        if (t == 0) {
            size_t o = (size_t)(b * MAXPB + fb) * 3;
            g_part2[o + 0] = (double)sf[0];
            g_part2[o + 1] = (double)sr[0];
            g_part2[o + 2] = (double)sn[0];
            __threadfence();
            int v = atomicAdd(&g_cnt2, 1);
            if (v == total_blocks - 1) s_final = 1;
        }
        __syncthreads();
        if (s_final) finalize(out, B, fblocks);
        return;
    }

    // ================= role 1: assign =================
    int i0 = blockIdx.x * ABLK;
    int i  = i0 + t;
    int lane = t & 31;

    __shared__ float sgx[MAXG][4], sgy[MAXG][4];
    __shared__ float sgb[MAXG][5];
    __shared__ float sg_sz[MAXG];
    __shared__ float sg_area[MAXG];
    __shared__ int   s_gl[MAXG];
    __shared__ unsigned long long s_best[MAXG];
    __shared__ unsigned long long s_bestA[ABLK];
    __shared__ float s_anc[ABLK][5];
    __shared__ float s_acx[ABLK][4], s_acy[ABLK][4];
    __shared__ unsigned short s_q[ABLK * 16];
    __shared__ int   s_qn;
    __shared__ int   s_last;
    __shared__ int   s_bi[MAXG], s_labv[MAXG], s_has[MAXG];

    if (t == 0) { s_qn = 0; s_last = 0; }
    if (t < G) {
        const float* gb = gt_boxes + (size_t)(b * G + t) * 5;
        float w = gb[2], h = gb[3];
        #pragma unroll
        for (int k = 0; k < 5; k++) sgb[t][k] = gb[k];
        sg_sz[t]   = fmaxf(w, h);
        sg_area[t] = w * h;
        s_gl[t]    = gt_labels[b * G + t];
        make_corners_f(gb[0], gb[1], w, h, gb[4], sgx[t], sgy[t]);
        s_best[t] = 0ULL;
    }
    s_bestA[t] = 0ULL;
    if (i < N) {
        const float* ab = anchors + (size_t)i * 5;
        #pragma unroll
        for (int k = 0; k < 5; k++) s_anc[t][k] = ab[k];
        make_corners_f(0.0f, 0.0f, ab[2], ab[3], ab[4], s_acx[t], s_acy[t]);
    }
    __syncthreads();

    // phase 1: gate -> per-thread mask -> warp-aggregated queue append
    {
        unsigned mask = 0;
        if (i < N) {
            float ax = s_anc[t][0], ay = s_anc[t][1];
            float a_sz = fmaxf(s_anc[t][2], s_anc[t][3]);
            for (int j = 0; j < G; j++) {
                float dx = ax - sgb[j][0];
                float dy = ay - sgb[j][1];
                float gate = (a_sz + sg_sz[j]) * 0.7f;
                if (sqrtf(dx * dx + dy * dy) < gate) mask |= (1u << j);
            }
        }
        int cnt = __popc(mask);
        int incl = cnt;
        #pragma unroll
        for (int d = 1; d < 32; d <<= 1) {
            int v = __shfl_up_sync(0xFFFFFFFFu, incl, d);
            if (lane >= d) incl += v;
        }
        int wtotal = __shfl_sync(0xFFFFFFFFu, incl, 31);
        int wbase = 0;
        if (lane == 31 && wtotal > 0) wbase = atomicAdd(&s_qn, wtotal);
        wbase = __shfl_sync(0xFFFFFFFFu, wbase, 31);
        int pos = wbase + incl - cnt;
        unsigned m = mask;
        while (m) {
            int j = __ffs(m) - 1;
            m &= m - 1;
            s_q[pos++] = (unsigned short)((t << 5) | j);
        }
    }
    __syncthreads();

    // phase 2: drain queue (register-resident clip)
    int qn = s_qn;
    for (int q = t; q < qn; q += ABLK) {
        int e  = s_q[q];
        int li = e >> 5;
        int j  = e & 31;

        float axc = s_anc[li][0], ayc = s_anc[li][1];
        float pa[4], qa[4], pb[4], qb[4];
        #pragma unroll
        for (int k = 0; k < 4; k++) {
            pa[k] = s_acx[li][k];
            qa[k] = s_acy[li][k];
            pb[k] = sgx[j][k] - axc;
            qb[k] = sgy[j][k] - ayc;
        }
        float inter = 0.5f * (arcs_cross_sum(pa, qa, pb, qb)
                            + arcs_cross_sum(pb, qb, pa, qa));
        float a_area = s_anc[li][2] * s_anc[li][3];
        float iou = inter / (a_area + sg_area[j] - inter + 1e-8f);
        if (iou > 0.0f) {
            unsigned long long ka =
                ((unsigned long long)__float_as_uint(iou) << 32)
                | (unsigned long long)(unsigned)(MAXG - 1 - j);
            atomicMax(&s_bestA[li], ka);
            unsigned long long kg =
                ((unsigned long long)__float_as_uint(iou) << 32)
                | (unsigned long long)(0xFFFFFFFFu - (unsigned)(i0 + li));
            atomicMax(&s_best[j], kg);
        }
    }
    __syncthreads();

    // phase 3: labels
    if (i < N) {
        unsigned long long ka = s_bestA[t];
        float best_iou = __uint_as_float((unsigned)(ka >> 32));
        int   best_j   = MAXG - 1 - (int)(ka & 31u);
        int lab;
        if (best_iou >= 0.5f) {
            lab = s_gl[best_j] + 1;
            #pragma unroll
            for (int k = 0; k < 5; k++)
                g_mg[(size_t)(b * MAXN + i) * 5 + k] = sgb[best_j][k];
        } else {
            lab = (best_iou < 0.4f) ? 0 : -1;
        }
        g_lab[b * MAXN + i] = lab;
    }
    __syncthreads();

    if (t < G && s_best[t] != 0ULL)
        atomicMax(&g_best[b * MAXG + t], s_best[t]);

    __syncthreads();
    if (t == 0) {
        __threadfence();
        int v = atomicAdd(&g_cnt1[b], 1);
        if (v == ablocks - 1) s_last = 1;
    }
    __syncthreads();

    // force-match tail: parallel prefetch, thread-0 logic, release g_done
    if (s_last) {
        if (t == 0) __threadfence();
        __syncthreads();
        if (t < G) {
            unsigned long long key = g_best[b * MAXG + t];
            g_best[b * MAXG + t] = 0ULL;
            int has = (key >> 32) != 0ULL;
            s_has[t] = has;
            int bi = has ? (int)(0xFFFFFFFFu - (unsigned)(key & 0xFFFFFFFFu)) : 0;
            s_bi[t] = bi;
            s_labv[t] = has ? g_lab[b * MAXN + bi] : 0;
        }
        __syncthreads();
        if (t == 0) {
            for (int j = 0; j < G; j++) {
                if (s_has[j]) {
                    int bi = s_bi[j];
                    int gl = s_gl[j] + 1;
                    if (s_labv[j] != gl) {
                        g_lab[b * MAXN + bi] = gl;
                        float* mgp = &g_mg[(size_t)(b * MAXN + bi) * 5];
                        #pragma unroll
                        for (int k = 0; k < 5; k++) mgp[k] = sgb[j][k];
                        for (int j2 = j + 1; j2 < G; j2++)
                            if (s_has[j2] && s_bi[j2] == bi) s_labv[j2] = gl;
                    }
                }
            }
            g_cnt1[b] = 0;
            __threadfence();
            g_done[b] = 1;
        }
    }
    __syncthreads();

    if (t == 0) {
        __threadfence();
        int v = atomicAdd(&g_cnt2, 1);
        if (v == total_blocks - 1) s_final = 1;
    }
    __syncthreads();
    if (s_final) finalize(out, B, fblocks);
}

// ---------------- launch ----------------
extern "C" void kernel_launch(void* const* d_in, const int* in_sizes, int n_in,
                              void* d_out, int out_size)
{
    const float* logits  = (const float*)d_in[0];
    const float* breg    = (const float*)d_in[1];
    const float* anchors = (const float*)d_in[2];
    const float* gtb     = (const float*)d_in[3];
    const int*   gtl     = (const int*)d_in[4];

    int N = in_sizes[2] / 5;
    int B = in_sizes[1] / (5 * N);
    int C = in_sizes[0] / (B * N);
    int G = in_sizes[4] / B;

    int ablocks = (N + ABLK - 1) / ABLK;
    int fblocks = FBLKS;

    dim3 mg(ablocks + fblocks, B);
    mega_kernel<<<mg, ABLK>>>(anchors, gtb, gtl, logits, breg,
                              (float*)d_out, N, G, C, B, ablocks, fblocks);
}